// round 14
// baseline (speedup 1.0000x reference)
#include <cuda_runtime.h>
#include <cuda_bf16.h>
#include <math.h>
#include <stdint.h>

#define N_NODES 20000
#define N_EDGES 100000
#define N_TRI   200000
#define NORB    16
#define EMB     128
#define CONV    64

#define N_TILES 12500       // k_cst: 8 edges (128 rows) per tile
#define PGRID   456         // k_cst persistent grid
#define N_NCHUNK 625        // node chunks of 32 nodes
#define N_ETILES 782        // k_edge: 128 edges per tile
#define PGRID_E  304        // k_edge persistent grid (152 SM x 2, fully resident)
#define N_OTILES 625        // out tiles of 32 nodes

typedef unsigned long long u64;

__device__ __forceinline__ float tanh_f(float x) {
    float r; asm("tanh.approx.f32 %0, %1;" : "=f"(r) : "f"(x)); return r;
}
__device__ __forceinline__ float silu_f(float x) {
    float h = 0.5f * x;
    return fmaf(h, tanh_f(h), h);
}
__device__ __forceinline__ float sigmoid_f(float x) {
    return fmaf(0.5f, tanh_f(0.5f * x), 0.5f);
}
__device__ __forceinline__ void red2(float* p, float a, float b) {
    asm volatile("red.global.add.v2.f32 [%0], {%1, %2};" :: "l"(p), "f"(a), "f"(b) : "memory");
}
__device__ __forceinline__ uint32_t smem_u32(const void* p) {
    uint32_t a;
    asm("{ .reg .u64 t; cvta.to.shared.u64 t, %1; cvt.u32.u64 %0, t; }" : "=r"(a) : "l"(p));
    return a;
}
__device__ __forceinline__ void cpa16(uint32_t dst, const void* src) {
    asm volatile("cp.async.ca.shared.global [%0], [%1], 16;" :: "r"(dst), "l"(src) : "memory");
}
__device__ __forceinline__ void cpa_commit() {
    asm volatile("cp.async.commit_group;" ::: "memory");
}
__device__ __forceinline__ void cpa_wait0() {
    asm volatile("cp.async.wait_group 0;" ::: "memory");
}
__device__ __forceinline__ void mma_bf16(float d[4], const uint32_t a[4],
                                         uint32_t b0, uint32_t b1) {
    asm("mma.sync.aligned.m16n8k16.row.col.f32.bf16.bf16.f32 "
        "{%0,%1,%2,%3}, {%4,%5,%6,%7}, {%8,%9}, {%0,%1,%2,%3};"
        : "+f"(d[0]), "+f"(d[1]), "+f"(d[2]), "+f"(d[3])
        : "r"(a[0]), "r"(a[1]), "r"(a[2]), "r"(a[3]), "r"(b0), "r"(b1));
}
__device__ __forceinline__ void ldmx4(uint32_t &r0, uint32_t &r1, uint32_t &r2,
                                      uint32_t &r3, uint32_t addr) {
    asm volatile("ldmatrix.sync.aligned.m8n8.x4.shared.b16 {%0,%1,%2,%3}, [%4];"
                 : "=r"(r0), "=r"(r1), "=r"(r2), "=r"(r3) : "r"(addr));
}
__device__ __forceinline__ unsigned bf2x(float lo, float hi) {
    __nv_bfloat162 h = __float22bfloat162_rn(make_float2(lo, hi));
    return *reinterpret_cast<unsigned*>(&h);
}

#define A_OFF(lane, ld) ((uint32_t)(((lane) & 15) * (ld) + (((lane) >> 4) << 3)) * 2u)
#define B_OFF(lane, ld) ((uint32_t)(((((lane) >> 4) << 3) + ((lane) & 7)) * (ld) + \
                                    ((((lane) >> 3) & 1) << 3)) * 2u)
#define PACK_A(dst, src, ks) do { \
    dst[0] = bf2x(src[2*(ks)][0],   src[2*(ks)][1]); \
    dst[1] = bf2x(src[2*(ks)][2],   src[2*(ks)][3]); \
    dst[2] = bf2x(src[2*(ks)+1][0], src[2*(ks)+1][1]); \
    dst[3] = bf2x(src[2*(ks)+1][2], src[2*(ks)+1][3]); \
} while (0)

// ---------- scratch ----------
__device__ float g_x1   [(size_t)N_NODES * CONV];
__device__ float g_xksig[(size_t)N_NODES * CONV];
__device__ __align__(16) __nv_bfloat16 g_cst2h[(size_t)N_EDGES * NORB * CONV];
__device__ float g_lraw [(size_t)N_EDGES * CONV];
__device__ float g_tbw  [(size_t)N_EDGES * CONV];
__device__ float g_agg  [(size_t)N_NODES * CONV];
// grid barrier state (sense-reversing; replay-safe: count returns to 0, sense monotonic)
__device__ unsigned g_bcount = 0;
__device__ volatile unsigned g_bsense = 0;

__device__ __forceinline__ void grid_bar(unsigned n) {
    __syncthreads();
    if (threadIdx.x == 0) {
        __threadfence();
        unsigned s = g_bsense;
        if (atomicAdd(&g_bcount, 1u) == n - 1u) {
            g_bcount = 0;
            __threadfence();
            g_bsense = s + 1u;
        } else {
            while (g_bsense == s) { }
        }
    }
    __syncthreads();
}

// ---------- K2: fused node-transform + persistent double-GEMM (R13 form) ----------
#define LDB 72
#define CST_SMEM_BYTES (18432 + 9216 + 9216 + 32768)
__global__ void __launch_bounds__(256, 3) k_cst_mma(const float* __restrict__ A,
                                                    const float* __restrict__ rb,
                                                    const float* __restrict__ x,
                                                    const float* __restrict__ Wn,
                                                    const float* __restrict__ bn,
                                                    const float* __restrict__ W1g,
                                                    const float* __restrict__ W2g) {
    extern __shared__ __align__(16) char smc[];
    __nv_bfloat16* sA  = (__nv_bfloat16*)smc;
    __nv_bfloat16* sW1 = (__nv_bfloat16*)(smc + 18432);
    __nv_bfloat16* sW2 = (__nv_bfloat16*)(smc + 27648);
    float*        stg  = (float*)(smc + 36864);
    const uint32_t sAu  = smem_u32(sA);
    const uint32_t sW1u = smem_u32(sW1);
    const uint32_t sW2u = smem_u32(sW2);
    const uint32_t stgu = smem_u32(stg);

    const int tid = threadIdx.x, wid = tid >> 5, lane = tid & 31;
    const int g = lane >> 2, tg = lane & 3;
    const int wr0 = wid * 16;

    for (int i = tid; i < 4096; i += 256) {
        int k = i >> 6, n = i & 63;
        sW1[n * LDB + k] = __float2bfloat16(W1g[i]);
        sW2[n * LDB + k] = __float2bfloat16(W2g[i]);
    }

    // ===== phase 1: node transform chunks =====
    const float4 z4 = make_float4(0.f, 0.f, 0.f, 0.f);
    for (int c = blockIdx.x; c < N_NCHUNK; c += PGRID) {
        __syncthreads();
        float* xs = stg;
        const int n0 = c * 32;
        for (int i = tid; i < 1024; i += 256)
            ((float4*)xs)[i] = ((const float4*)x)[(size_t)n0 * 32 + i];
        ((float4*)g_agg)[(size_t)c * 512 + tid]       = z4;
        ((float4*)g_agg)[(size_t)c * 512 + tid + 256] = z4;
        __syncthreads();
        const int col = tid & 127, half = tid >> 7;
        float acc[16];
        float b = bn[col];
#pragma unroll
        for (int v = 0; v < 16; v++) acc[v] = b;
#pragma unroll 4
        for (int k = 0; k < EMB; k++) {
            float w = Wn[k * EMB + col];
#pragma unroll
            for (int v = 0; v < 16; v++)
                acc[v] = fmaf(xs[(half * 16 + v) * EMB + k], w, acc[v]);
        }
        if (col < CONV) {
#pragma unroll
            for (int v = 0; v < 16; v++)
                g_x1[(size_t)(n0 + half * 16 + v) * CONV + col] = acc[v];
        } else {
            int jj = col - CONV;
#pragma unroll
            for (int v = 0; v < 16; v++)
                g_xksig[(size_t)(n0 + half * 16 + v) * CONV + jj] = sigmoid_f(acc[v]);
        }
    }
    __syncthreads();

    // ===== phase 2: persistent cst double-GEMM =====
    if (blockIdx.x < N_TILES) {
        const float4* src = (const float4*)(A + (size_t)blockIdx.x * 8192);
#pragma unroll
        for (int j = 0; j < 8; j++)
            cpa16(stgu + (tid + 256 * j) * 16, src + tid + 256 * j);
        cpa_commit();
    }

    const uint32_t a_off = A_OFF(lane, LDB);
    const uint32_t b_off = B_OFF(lane, LDB);

    for (int tile = blockIdx.x; tile < N_TILES; tile += PGRID) {
        cpa_wait0();
        __syncthreads();
#pragma unroll
        for (int j = 0; j < 8; j++) {
            int idx = tid + 256 * j;
            int r = idx >> 4, c4 = idx & 15;
            float4 v = *(const float4*)(stg + idx * 4);
            *(uint2*)(sA + r * LDB + c4 * 4) = make_uint2(bf2x(v.x, v.y), bf2x(v.z, v.w));
        }
        __syncthreads();
        {
            int nt = tile + PGRID;
            if (nt < N_TILES) {
                const float4* src = (const float4*)(A + (size_t)nt * 8192);
#pragma unroll
                for (int j = 0; j < 8; j++)
                    cpa16(stgu + (tid + 256 * j) * 16, src + tid + 256 * j);
                cpa_commit();
            }
        }
        if (tid < 128)
            ((float4*)g_tbw)[(size_t)tile * 128 + tid] = z4;

        float acc[8][4];
        uint32_t a[4];

#pragma unroll
        for (int at = 0; at < 8; at++)
#pragma unroll
            for (int q = 0; q < 4; q++) acc[at][q] = 0.f;
#pragma unroll
        for (int ks = 0; ks < 4; ks++) {
            const int k0 = ks * 16;
            ldmx4(a[0], a[1], a[2], a[3], sAu + a_off + (uint32_t)(wr0 * LDB + k0) * 2);
#pragma unroll
            for (int np = 0; np < 4; np++) {
                uint32_t b0, b1, b2, b3;
                ldmx4(b0, b1, b2, b3, sW1u + b_off + (uint32_t)(np * 16 * LDB + k0) * 2);
                mma_bf16(acc[2 * np],     a, b0, b1);
                mma_bf16(acc[2 * np + 1], a, b2, b3);
            }
        }
        uint32_t aa[4][4];
#pragma unroll
        for (int at = 0; at < 8; at++)
#pragma unroll
            for (int q = 0; q < 4; q++) acc[at][q] = silu_f(acc[at][q]);
#pragma unroll
        for (int ks = 0; ks < 4; ks++) PACK_A(aa[ks], acc, ks);

#pragma unroll
        for (int at = 0; at < 8; at++)
#pragma unroll
            for (int q = 0; q < 4; q++) acc[at][q] = 0.f;
#pragma unroll
        for (int ks = 0; ks < 4; ks++) {
            const int k0 = ks * 16;
#pragma unroll
            for (int np = 0; np < 4; np++) {
                uint32_t b0, b1, b2, b3;
                ldmx4(b0, b1, b2, b3, sW2u + b_off + (uint32_t)(np * 16 * LDB + k0) * 2);
                mma_bf16(acc[2 * np],     aa[ks], b0, b1);
                mma_bf16(acc[2 * np + 1], aa[ks], b2, b3);
            }
        }

        {
            const int edge = tile * 8 + wid;
            float rbl = (lane < NORB) ? rb[(size_t)edge * NORB + lane] : 0.f;
            float rbg  = __shfl_sync(0xffffffffu, rbl, g);
            float rbg8 = __shfl_sync(0xffffffffu, rbl, g + 8);
#pragma unroll
            for (int at = 0; at < 8; at++) {
                float v0 = silu_f(acc[at][0]);
                float v1 = silu_f(acc[at][1]);
                float v2 = silu_f(acc[at][2]);
                float v3 = silu_f(acc[at][3]);
                int c = at * 8 + 2 * tg;
                *(unsigned*)(sA + (wr0 + g) * LDB + c)     = bf2x(v0, v1);
                *(unsigned*)(sA + (wr0 + g + 8) * LDB + c) = bf2x(v2, v3);
                float c0 = rbg * v0 + rbg8 * v2;
                float c1 = rbg * v1 + rbg8 * v3;
#pragma unroll
                for (int o = 4; o < 32; o <<= 1) {
                    c0 += __shfl_xor_sync(0xffffffffu, c0, o);
                    c1 += __shfl_xor_sync(0xffffffffu, c1, o);
                }
                if (lane < 4)
                    *(float2*)&g_lraw[(size_t)edge * CONV + at * 8 + 2 * tg] =
                        make_float2(c0, c1);
            }
        }
        __syncwarp();
        {
            int r = wr0 + (lane >> 1);
            int j0 = (lane & 1) * 4;
            size_t grow = (size_t)tile * 128 + r;
            uint4* dst = (uint4*)(g_cst2h + grow * 64);
            const __nv_bfloat16* src = sA + r * LDB;
#pragma unroll
            for (int j = 0; j < 4; j++)
                dst[j0 + j] = *(const uint4*)(src + (j0 + j) * 8);
        }
    }
}

// ---------- K3: triplet kernel, 2/warp, batched loads, early sg loads ----------
__global__ void __launch_bounds__(256) k_tri(const float* __restrict__ rb,
                                             const float* __restrict__ shb,
                                             const int*   __restrict__ tri_k,
                                             const int*   __restrict__ eks,
                                             const int*   __restrict__ est) {
    int w = (blockIdx.x * blockDim.x + threadIdx.x) >> 5;
    int lane = threadIdx.x & 31;
    int t0 = 2 * w, t1 = 2 * w + 1;
    if (t0 >= N_TRI) return;

    int e0 = eks[t0], k0 = tri_k[t0], o0 = est[t0];
    int e1 = eks[t1], k1 = tri_k[t1], o1 = est[t1];

    float cl0 = (lane < NORB) ? rb[(size_t)e0 * NORB + lane] * shb[(size_t)t0 * NORB + lane] : 0.f;
    float cl1 = (lane < NORB) ? rb[(size_t)e1 * NORB + lane] * shb[(size_t)t1 * NORB + lane] : 0.f;

    // hoist sigmoid-gate loads (extra MLP)
    float2 sg0 = *(const float2*)(g_xksig + (size_t)k0 * CONV + 2 * lane);
    float2 sg1 = *(const float2*)(g_xksig + (size_t)k1 * CONV + 2 * lane);

    const uint32_t* C0 = (const uint32_t*)(g_cst2h + (size_t)e0 * (NORB * CONV));
    const uint32_t* C1 = (const uint32_t*)(g_cst2h + (size_t)e1 * (NORB * CONV));
    uint32_t r0[NORB], r1[NORB];
#pragma unroll
    for (int d = 0; d < NORB; d++) r0[d] = C0[d * 32 + lane];
#pragma unroll
    for (int d = 0; d < NORB; d++) r1[d] = C1[d * 32 + lane];

    float a0 = 0.f, a1 = 0.f, b0 = 0.f, b1 = 0.f;
#pragma unroll
    for (int d = 0; d < NORB; d++) {
        float c0 = __shfl_sync(0xffffffffu, cl0, d);
        float c1 = __shfl_sync(0xffffffffu, cl1, d);
        float2 v0 = __bfloat1622float2(*(const __nv_bfloat162*)&r0[d]);
        float2 v1 = __bfloat1622float2(*(const __nv_bfloat162*)&r1[d]);
        a0 = fmaf(c0, v0.x, a0);
        a1 = fmaf(c0, v0.y, a1);
        b0 = fmaf(c1, v1.x, b0);
        b1 = fmaf(c1, v1.y, b1);
    }
    float sa = a0 * a0 + a1 * a1;
    float sbb = b0 * b0 + b1 * b1;
#pragma unroll
    for (int o = 16; o; o >>= 1) {
        sa  += __shfl_xor_sync(0xffffffffu, sa, o);
        sbb += __shfl_xor_sync(0xffffffffu, sbb, o);
    }
    float ia = 1.f / fmaxf(sqrtf(sa), 1e-12f);
    float ib = 1.f / fmaxf(sqrtf(sbb), 1e-12f);

    red2(&g_tbw[(size_t)o0 * CONV + 2 * lane], a0 * ia * sg0.x, a1 * ia * sg0.y);
    red2(&g_tbw[(size_t)o1 * CONV + 2 * lane], b0 * ib * sg1.x, b1 * ib * sg1.y);
}

// ---------- K4: persistent edge kernel + grid barrier + fused out-projection ----------
#define E_W3   0
#define E_WB   4608
#define E_WN2  9216
#define E_WN1  13824
#define E_TW   22528
#define E_CAT  31744
#define E_END  49152
#define LDC    136
#define EDGE_SMEM_BYTES (E_END * 2 + 512 + 1024)
__global__ void __launch_bounds__(256, 2) k_edge(const int* __restrict__ idx_s,
                                                 const int* __restrict__ idx_t,
                                                 const float* __restrict__ W3g,
                                                 const float* __restrict__ Wbg,
                                                 const float* __restrict__ Wn1g,
                                                 const float* __restrict__ bn1g,
                                                 const float* __restrict__ Wn2g,
                                                 const float* __restrict__ bn2g,
                                                 const float* __restrict__ x,
                                                 const float* __restrict__ Wout,
                                                 float* __restrict__ out) {
    extern __shared__ __align__(16) __nv_bfloat16 sb[];
    __nv_bfloat16* sW3  = sb + E_W3;
    __nv_bfloat16* sWB  = sb + E_WB;
    __nv_bfloat16* sWN2 = sb + E_WN2;
    __nv_bfloat16* sWN1 = sb + E_WN1;
    __nv_bfloat16* sTW  = sb + E_TW;
    __nv_bfloat16* sCAT = sb + E_CAT;
    float* b1s = (float*)(sb + E_END);
    float* b2s = b1s + 64;
    int*   es  = (int*)(b2s + 64);
    int*   et  = es + 128;
    const uint32_t sW3u  = smem_u32(sW3);
    const uint32_t sWBu  = smem_u32(sWB);
    const uint32_t sWN2u = smem_u32(sWN2);
    const uint32_t sWN1u = smem_u32(sWN1);
    const uint32_t sTWu  = smem_u32(sTW);
    const uint32_t sCATu = smem_u32(sCAT);

    const int tid = threadIdx.x, wid = tid >> 5, lane = tid & 31;
    const int g = lane >> 2, tg = lane & 3;
    const int wr0 = wid * 16;

    for (int i = tid; i < 4096; i += 256) {
        int k = i >> 6, n = i & 63;
        sW3 [n * LDB + k] = __float2bfloat16(W3g[i]);
        sWB [n * LDB + k] = __float2bfloat16(Wbg[i]);
        sWN2[n * LDB + k] = __float2bfloat16(Wn2g[i]);
    }
    for (int i = tid; i < 8192; i += 256) {
        int k = i >> 6, n = i & 63;
        sWN1[n * LDC + k] = __float2bfloat16(Wn1g[i]);
    }
    if (tid < 64) { b1s[tid] = bn1g[tid]; b2s[tid] = bn2g[tid]; }

    const uint32_t a_offB = A_OFF(lane, LDB);
    const uint32_t b_offB = B_OFF(lane, LDB);
    const uint32_t a_offC = A_OFF(lane, LDC);
    const uint32_t b_offC = B_OFF(lane, LDC);

    for (int tile = blockIdx.x; tile < N_ETILES; tile += PGRID_E) {
        const int e0 = tile * 128;
        __syncthreads();

        if (tid < 128) {
            int e = e0 + tid;
            es[tid] = (e < N_EDGES) ? idx_s[e] : 0;
            et[tid] = (e < N_EDGES) ? idx_t[e] : 0;
        }
        for (int i = tid; i < 2048; i += 256) {
            int r = i >> 4, c4 = i & 15;
            float4 v = (e0 + r < N_EDGES) ? ((const float4*)g_tbw)[(size_t)(e0 + r) * 16 + c4]
                                          : make_float4(0.f, 0.f, 0.f, 0.f);
            *(uint2*)(sTW + r * LDB + c4 * 4) = make_uint2(bf2x(v.x, v.y), bf2x(v.z, v.w));
        }
        __syncthreads();

        for (int i = tid; i < 4096; i += 256) {
            int r = i >> 5, c4 = i & 31;
            int node = (c4 < 16) ? es[r] : et[r];
            float4 v = (e0 + r < N_EDGES) ? ((const float4*)g_x1)[(size_t)node * 16 + (c4 & 15)]
                                          : make_float4(0.f, 0.f, 0.f, 0.f);
            *(uint2*)(sCAT + r * LDC + c4 * 4) = make_uint2(bf2x(v.x, v.y), bf2x(v.z, v.w));
        }

        float acc[8][4];
        uint32_t a[4];
        uint32_t la[4][4];
        uint32_t na[4][4];

        // ---- GEMM1: proj = tw @ W3 -> lc (overlaps cat gather) ----
#pragma unroll
        for (int at = 0; at < 8; at++)
#pragma unroll
            for (int q = 0; q < 4; q++) acc[at][q] = 0.f;
#pragma unroll
        for (int ks = 0; ks < 4; ks++) {
            const int k0 = ks * 16;
            ldmx4(a[0], a[1], a[2], a[3], sTWu + a_offB + (uint32_t)(wr0 * LDB + k0) * 2);
#pragma unroll
            for (int np = 0; np < 4; np++) {
                uint32_t b0, b1, b2, b3;
                ldmx4(b0, b1, b2, b3, sW3u + b_offB + (uint32_t)(np * 16 * LDB + k0) * 2);
                mma_bf16(acc[2 * np],     a, b0, b1);
                mma_bf16(acc[2 * np + 1], a, b2, b3);
            }
        }
        {
            size_t eg  = (size_t)(e0 + wr0 + g);
            size_t eg8 = eg + 8;
            bool ok0 = eg  < N_EDGES;
            bool ok8 = eg8 < N_EDGES;
            float s0 = 0.f, s8 = 0.f;
#pragma unroll
            for (int at = 0; at < 8; at++) {
                int c = at * 8 + 2 * tg;
                float2 l0 = ok0 ? *(const float2*)&g_lraw[eg * CONV + c]  : make_float2(0.f, 0.f);
                float2 l8 = ok8 ? *(const float2*)&g_lraw[eg8 * CONV + c] : make_float2(0.f, 0.f);
                acc[at][0] = l0.x * (1.f + acc[at][0]);
                acc[at][1] = l0.y * (1.f + acc[at][1]);
                acc[at][2] = l8.x * (1.f + acc[at][2]);
                acc[at][3] = l8.y * (1.f + acc[at][3]);
                s0 += acc[at][0] * acc[at][0] + acc[at][1] * acc[at][1];
                s8 += acc[at][2] * acc[at][2] + acc[at][3] * acc[at][3];
            }
#pragma unroll
            for (int o = 1; o < 4; o <<= 1) {
                s0 += __shfl_xor_sync(0xffffffffu, s0, o);
                s8 += __shfl_xor_sync(0xffffffffu, s8, o);
            }
            float i0 = 1.f / fmaxf(sqrtf(s0), 1e-12f);
            float i8 = 1.f / fmaxf(sqrtf(s8), 1e-12f);
#pragma unroll
            for (int at = 0; at < 8; at++) {
                acc[at][0] *= i0; acc[at][1] *= i0;
                acc[at][2] *= i8; acc[at][3] *= i8;
            }
#pragma unroll
            for (int ks = 0; ks < 4; ks++) PACK_A(la[ks], acc, ks);
        }
        __syncthreads();

        // ---- GEMM2: n1 = silu(cat @ Wn1 + b1) ----
#pragma unroll
        for (int at = 0; at < 8; at++) {
            int c = at * 8 + 2 * tg;
            acc[at][0] = b1s[c]; acc[at][1] = b1s[c + 1];
            acc[at][2] = acc[at][0]; acc[at][3] = acc[at][1];
        }
#pragma unroll
        for (int ks = 0; ks < 8; ks++) {
            const int k0 = ks * 16;
            ldmx4(a[0], a[1], a[2], a[3], sCATu + a_offC + (uint32_t)(wr0 * LDC + k0) * 2);
#pragma unroll
            for (int np = 0; np < 4; np++) {
                uint32_t b0, b1, b2, b3;
                ldmx4(b0, b1, b2, b3, sWN1u + b_offC + (uint32_t)(np * 16 * LDC + k0) * 2);
                mma_bf16(acc[2 * np],     a, b0, b1);
                mma_bf16(acc[2 * np + 1], a, b2, b3);
            }
        }
#pragma unroll
        for (int at = 0; at < 8; at++)
#pragma unroll
            for (int q = 0; q < 4; q++) acc[at][q] = silu_f(acc[at][q]);
#pragma unroll
        for (int ks = 0; ks < 4; ks++) PACK_A(na[ks], acc, ks);

        // ---- GEMM3: nf = silu(n1 @ Wn2 + b2) ----
        float nf[8][4];
#pragma unroll
        for (int at = 0; at < 8; at++) {
            int c = at * 8 + 2 * tg;
            nf[at][0] = b2s[c]; nf[at][1] = b2s[c + 1];
            nf[at][2] = nf[at][0]; nf[at][3] = nf[at][1];
        }
#pragma unroll
        for (int ks = 0; ks < 4; ks++) {
            const int k0 = ks * 16;
#pragma unroll
            for (int np = 0; np < 4; np++) {
                uint32_t b0, b1, b2, b3;
                ldmx4(b0, b1, b2, b3, sWN2u + b_offB + (uint32_t)(np * 16 * LDB + k0) * 2);
                mma_bf16(nf[2 * np],     na[ks], b0, b1);
                mma_bf16(nf[2 * np + 1], na[ks], b2, b3);
            }
        }
#pragma unroll
        for (int at = 0; at < 8; at++)
#pragma unroll
            for (int q = 0; q < 4; q++) nf[at][q] = silu_f(nf[at][q]);

        // ---- GEMM4: m = lc @ Wb ----
#pragma unroll
        for (int at = 0; at < 8; at++)
#pragma unroll
            for (int q = 0; q < 4; q++) acc[at][q] = 0.f;
#pragma unroll
        for (int ks = 0; ks < 4; ks++) {
            const int k0 = ks * 16;
#pragma unroll
            for (int np = 0; np < 4; np++) {
                uint32_t b0, b1, b2, b3;
                ldmx4(b0, b1, b2, b3, sWBu + b_offB + (uint32_t)(np * 16 * LDB + k0) * 2);
                mma_bf16(acc[2 * np],     la[ks], b0, b1);
                mma_bf16(acc[2 * np + 1], la[ks], b2, b3);
            }
        }

        // ---- scatter msg = m * nf by idx_s ----
        {
            int rg = wr0 + g;
            int ns0 = es[rg], ns8 = es[rg + 8];
            bool ok0 = (e0 + rg) < N_EDGES;
            bool ok8 = (e0 + rg + 8) < N_EDGES;
#pragma unroll
            for (int at = 0; at < 8; at++) {
                int c = at * 8 + 2 * tg;
                if (ok0) red2(&g_agg[(size_t)ns0 * CONV + c],
                              acc[at][0] * nf[at][0], acc[at][1] * nf[at][1]);
                if (ok8) red2(&g_agg[(size_t)ns8 * CONV + c],
                              acc[at][2] * nf[at][2], acc[at][3] * nf[at][3]);
            }
        }
    }

    // ===== grid barrier: all red2 to g_agg complete =====
    grid_bar(PGRID_E);

    // ===== out phase: out = x + agg @ W_out, 32 nodes per tile =====
    float* ags = (float*)sTW;   // 8 KB scratch (sTW region free now)
    for (int t = blockIdx.x; t < N_OTILES; t += PGRID_E) {
        __syncthreads();
        const int n0 = t * 32;
        for (int i = tid; i < 512; i += 256)
            ((float4*)ags)[i] = ((const float4*)g_agg)[(size_t)t * 512 + i];
        __syncthreads();
        const int col = tid & 127, half = tid >> 7;
        float acc[16];
#pragma unroll
        for (int v = 0; v < 16; v++) acc[v] = 0.f;
#pragma unroll 4
        for (int k = 0; k < CONV; k++) {
            float w = Wout[k * EMB + col];
#pragma unroll
            for (int v = 0; v < 16; v++)
                acc[v] = fmaf(ags[(half * 16 + v) * CONV + k], w, acc[v]);
        }
#pragma unroll
        for (int v = 0; v < 16; v++) {
            size_t n = (size_t)(n0 + half * 16 + v);
            out[n * EMB + col] = x[n * EMB + col] + acc[v];
        }
    }
}

extern "C" void kernel_launch(void* const* d_in, const int* in_sizes, int n_in,
                              void* d_out, int out_size) {
    const float* x      = (const float*)d_in[0];
    const float* cst    = (const float*)d_in[1];
    const float* rb     = (const float*)d_in[2];
    const float* shb    = (const float*)d_in[3];
    const int*   idx_s  = (const int*)  d_in[4];
    const int*   idx_t  = (const int*)  d_in[5];
    const int*   tri_k  = (const int*)  d_in[6];
    const int*   eks    = (const int*)  d_in[7];
    const int*   est    = (const int*)  d_in[8];
    const float* W_node = (const float*)d_in[9];
    const float* b_node = (const float*)d_in[10];
    const float* W_c1   = (const float*)d_in[11];
    const float* W_c2   = (const float*)d_in[12];
    const float* W_three= (const float*)d_in[13];
    const float* W_basis= (const float*)d_in[14];
    const float* W_n1   = (const float*)d_in[15];
    const float* b_n1   = (const float*)d_in[16];
    const float* W_n2   = (const float*)d_in[17];
    const float* b_n2   = (const float*)d_in[18];
    const float* W_out  = (const float*)d_in[19];
    float* out = (float*)d_out;

    cudaFuncSetAttribute(k_edge,    cudaFuncAttributeMaxDynamicSharedMemorySize, EDGE_SMEM_BYTES);
    cudaFuncSetAttribute(k_cst_mma, cudaFuncAttributeMaxDynamicSharedMemorySize, CST_SMEM_BYTES);

    k_cst_mma<<<PGRID, 256, CST_SMEM_BYTES>>>(cst, rb, x, W_node, b_node, W_c1, W_c2);
    k_tri <<<N_TRI / 16, 256>>>(rb, shb, tri_k, eks, est);
    k_edge<<<PGRID_E, 256, EDGE_SMEM_BYTES>>>(idx_s, idx_t, W_three, W_basis,
                                              W_n1, b_n1, W_n2, b_n2,
                                              x, W_out, out);
}

// round 15
// speedup vs baseline: 1.1123x; 1.1123x over previous
#include <cuda_runtime.h>
#include <cuda_bf16.h>
#include <math.h>
#include <stdint.h>

#define N_NODES 20000
#define N_EDGES 100000
#define N_TRI   200000
#define NORB    16
#define EMB     128
#define CONV    64

#define N_TILES 12500       // k_cst: 8 edges (128 rows) per tile
#define PGRID   912         // k_cst persistent grid (152 SM x 6 max waves; 4 resident)
#define N_NCHUNK 625        // node chunks of 32 nodes
#define N_ETILES 782        // k_edge: 128 edges per tile
#define PGRID_E  304        // k_edge persistent grid

typedef unsigned long long u64;

__device__ __forceinline__ float tanh_f(float x) {
    float r; asm("tanh.approx.f32 %0, %1;" : "=f"(r) : "f"(x)); return r;
}
__device__ __forceinline__ float silu_f(float x) {
    float h = 0.5f * x;
    return fmaf(h, tanh_f(h), h);
}
__device__ __forceinline__ float sigmoid_f(float x) {
    return fmaf(0.5f, tanh_f(0.5f * x), 0.5f);
}
__device__ __forceinline__ void red2(float* p, float a, float b) {
    asm volatile("red.global.add.v2.f32 [%0], {%1, %2};" :: "l"(p), "f"(a), "f"(b) : "memory");
}
__device__ __forceinline__ uint32_t smem_u32(const void* p) {
    uint32_t a;
    asm("{ .reg .u64 t; cvta.to.shared.u64 t, %1; cvt.u32.u64 %0, t; }" : "=r"(a) : "l"(p));
    return a;
}
__device__ __forceinline__ void mma_bf16(float d[4], const uint32_t a[4],
                                         uint32_t b0, uint32_t b1) {
    asm("mma.sync.aligned.m16n8k16.row.col.f32.bf16.bf16.f32 "
        "{%0,%1,%2,%3}, {%4,%5,%6,%7}, {%8,%9}, {%0,%1,%2,%3};"
        : "+f"(d[0]), "+f"(d[1]), "+f"(d[2]), "+f"(d[3])
        : "r"(a[0]), "r"(a[1]), "r"(a[2]), "r"(a[3]), "r"(b0), "r"(b1));
}
__device__ __forceinline__ void ldmx4(uint32_t &r0, uint32_t &r1, uint32_t &r2,
                                      uint32_t &r3, uint32_t addr) {
    asm volatile("ldmatrix.sync.aligned.m8n8.x4.shared.b16 {%0,%1,%2,%3}, [%4];"
                 : "=r"(r0), "=r"(r1), "=r"(r2), "=r"(r3) : "r"(addr));
}
__device__ __forceinline__ unsigned bf2x(float lo, float hi) {
    __nv_bfloat162 h = __float22bfloat162_rn(make_float2(lo, hi));
    return *reinterpret_cast<unsigned*>(&h);
}

#define A_OFF(lane, ld) ((uint32_t)(((lane) & 15) * (ld) + (((lane) >> 4) << 3)) * 2u)
#define B_OFF(lane, ld) ((uint32_t)(((((lane) >> 4) << 3) + ((lane) & 7)) * (ld) + \
                                    ((((lane) >> 3) & 1) << 3)) * 2u)
#define PACK_A(dst, src, ks) do { \
    dst[0] = bf2x(src[2*(ks)][0],   src[2*(ks)][1]); \
    dst[1] = bf2x(src[2*(ks)][2],   src[2*(ks)][3]); \
    dst[2] = bf2x(src[2*(ks)+1][0], src[2*(ks)+1][1]); \
    dst[3] = bf2x(src[2*(ks)+1][2], src[2*(ks)+1][3]); \
} while (0)

// ---------- scratch ----------
__device__ float g_x1   [(size_t)N_NODES * CONV];
__device__ float g_xksig[(size_t)N_NODES * CONV];
__device__ __align__(16) __nv_bfloat16 g_cst2h[(size_t)N_EDGES * NORB * CONV];
__device__ float g_lraw [(size_t)N_EDGES * CONV];
__device__ float g_tbw  [(size_t)N_EDGES * CONV];
__device__ float g_agg  [(size_t)N_NODES * CONV];

// ---------- K2: fused node-transform + persistent double-GEMM, 4 CTAs/SM ----------
// smem: sA bf16 128x72 (18432) | W1 9216 | W2 9216 = 36864 B
#define LDB 72
#define CST_SMEM_BYTES (18432 + 9216 + 9216)
__global__ void __launch_bounds__(256, 4) k_cst_mma(const float* __restrict__ A,
                                                    const float* __restrict__ rb,
                                                    const float* __restrict__ x,
                                                    const float* __restrict__ Wn,
                                                    const float* __restrict__ bn,
                                                    const float* __restrict__ W1g,
                                                    const float* __restrict__ W2g) {
    extern __shared__ __align__(16) char smc[];
    __nv_bfloat16* sA  = (__nv_bfloat16*)smc;
    __nv_bfloat16* sW1 = (__nv_bfloat16*)(smc + 18432);
    __nv_bfloat16* sW2 = (__nv_bfloat16*)(smc + 27648);
    const uint32_t sAu  = smem_u32(sA);
    const uint32_t sW1u = smem_u32(sW1);
    const uint32_t sW2u = smem_u32(sW2);

    const int tid = threadIdx.x, wid = tid >> 5, lane = tid & 31;
    const int g = lane >> 2, tg = lane & 3;
    const int wr0 = wid * 16;

    for (int i = tid; i < 4096; i += 256) {
        int k = i >> 6, n = i & 63;
        sW1[n * LDB + k] = __float2bfloat16(W1g[i]);
        sW2[n * LDB + k] = __float2bfloat16(W2g[i]);
    }

    // ===== phase 1: node transform chunks (xs lives in the sA region, 16KB) =====
    const float4 z4 = make_float4(0.f, 0.f, 0.f, 0.f);
    float* xs = (float*)sA;
    for (int c = blockIdx.x; c < N_NCHUNK; c += PGRID) {
        __syncthreads();
        const int n0 = c * 32;
        for (int i = tid; i < 1024; i += 256)
            ((float4*)xs)[i] = ((const float4*)x)[(size_t)n0 * 32 + i];
        ((float4*)g_agg)[(size_t)c * 512 + tid]       = z4;
        ((float4*)g_agg)[(size_t)c * 512 + tid + 256] = z4;
        __syncthreads();
        const int col = tid & 127, half = tid >> 7;
        float acc[16];
        float b = bn[col];
#pragma unroll
        for (int v = 0; v < 16; v++) acc[v] = b;
#pragma unroll 4
        for (int k = 0; k < EMB; k++) {
            float w = Wn[k * EMB + col];
#pragma unroll
            for (int v = 0; v < 16; v++)
                acc[v] = fmaf(xs[(half * 16 + v) * EMB + k], w, acc[v]);
        }
        if (col < CONV) {
#pragma unroll
            for (int v = 0; v < 16; v++)
                g_x1[(size_t)(n0 + half * 16 + v) * CONV + col] = acc[v];
        } else {
            int jj = col - CONV;
#pragma unroll
            for (int v = 0; v < 16; v++)
                g_xksig[(size_t)(n0 + half * 16 + v) * CONV + jj] = sigmoid_f(acc[v]);
        }
    }

    // ===== phase 2: persistent cst double-GEMM (direct LDG fill, smem roundtrip) =====
    const uint32_t a_off = A_OFF(lane, LDB);
    const uint32_t b_off = B_OFF(lane, LDB);

    for (int tile = blockIdx.x; tile < N_TILES; tile += PGRID) {
        __syncthreads();   // sA free (all warps past previous epilogue / phase-1)
        // direct coalesced LDG of fp32 tile (MLP 8), convert, STS bf16
        {
            const float4* src = (const float4*)(A + (size_t)tile * 8192);
            float4 v[8];
#pragma unroll
            for (int j = 0; j < 8; j++) v[j] = src[tid + 256 * j];
            if (tid < 128)
                ((float4*)g_tbw)[(size_t)tile * 128 + tid] = z4;
#pragma unroll
            for (int j = 0; j < 8; j++) {
                int idx = tid + 256 * j;
                int r = idx >> 4, c4 = idx & 15;
                *(uint2*)(sA + r * LDB + c4 * 4) =
                    make_uint2(bf2x(v[j].x, v[j].y), bf2x(v[j].z, v[j].w));
            }
        }
        __syncthreads();

        float acc[8][4];
        uint32_t a[4];

        // ---- stage 1: Y = A @ W1 ----
#pragma unroll
        for (int at = 0; at < 8; at++)
#pragma unroll
            for (int q = 0; q < 4; q++) acc[at][q] = 0.f;
#pragma unroll
        for (int ks = 0; ks < 4; ks++) {
            const int k0 = ks * 16;
            ldmx4(a[0], a[1], a[2], a[3], sAu + a_off + (uint32_t)(wr0 * LDB + k0) * 2);
#pragma unroll
            for (int np = 0; np < 4; np++) {
                uint32_t b0, b1, b2, b3;
                ldmx4(b0, b1, b2, b3, sW1u + b_off + (uint32_t)(np * 16 * LDB + k0) * 2);
                mma_bf16(acc[2 * np],     a, b0, b1);
                mma_bf16(acc[2 * np + 1], a, b2, b3);
            }
        }
        // silu -> bf16 -> own rows of sA (warp-private), roundtrip for stage 2
#pragma unroll
        for (int at = 0; at < 8; at++) {
            int c = at * 8 + 2 * tg;
            *(unsigned*)(sA + (wr0 + g) * LDB + c) =
                bf2x(silu_f(acc[at][0]), silu_f(acc[at][1]));
            *(unsigned*)(sA + (wr0 + g + 8) * LDB + c) =
                bf2x(silu_f(acc[at][2]), silu_f(acc[at][3]));
        }
        __syncwarp();

        // ---- stage 2: Z = silu(Y) @ W2 ----
#pragma unroll
        for (int at = 0; at < 8; at++)
#pragma unroll
            for (int q = 0; q < 4; q++) acc[at][q] = 0.f;
#pragma unroll
        for (int ks = 0; ks < 4; ks++) {
            const int k0 = ks * 16;
            ldmx4(a[0], a[1], a[2], a[3], sAu + a_off + (uint32_t)(wr0 * LDB + k0) * 2);
#pragma unroll
            for (int np = 0; np < 4; np++) {
                uint32_t b0, b1, b2, b3;
                ldmx4(b0, b1, b2, b3, sW2u + b_off + (uint32_t)(np * 16 * LDB + k0) * 2);
                mma_bf16(acc[2 * np],     a, b0, b1);
                mma_bf16(acc[2 * np + 1], a, b2, b3);
            }
        }

        // ---- epilogue: silu, lraw, bf16 store via sA (warp-private rows) ----
        {
            const int edge = tile * 8 + wid;
            float rbl = (lane < NORB) ? rb[(size_t)edge * NORB + lane] : 0.f;
            float rbg  = __shfl_sync(0xffffffffu, rbl, g);
            float rbg8 = __shfl_sync(0xffffffffu, rbl, g + 8);
#pragma unroll
            for (int at = 0; at < 8; at++) {
                float v0 = silu_f(acc[at][0]);
                float v1 = silu_f(acc[at][1]);
                float v2 = silu_f(acc[at][2]);
                float v3 = silu_f(acc[at][3]);
                int c = at * 8 + 2 * tg;
                *(unsigned*)(sA + (wr0 + g) * LDB + c)     = bf2x(v0, v1);
                *(unsigned*)(sA + (wr0 + g + 8) * LDB + c) = bf2x(v2, v3);
                float c0 = rbg * v0 + rbg8 * v2;
                float c1 = rbg * v1 + rbg8 * v3;
#pragma unroll
                for (int o = 4; o < 32; o <<= 1) {
                    c0 += __shfl_xor_sync(0xffffffffu, c0, o);
                    c1 += __shfl_xor_sync(0xffffffffu, c1, o);
                }
                if (lane < 4)
                    *(float2*)&g_lraw[(size_t)edge * CONV + at * 8 + 2 * tg] =
                        make_float2(c0, c1);
            }
        }
        __syncwarp();
        {
            int r = wr0 + (lane >> 1);
            int j0 = (lane & 1) * 4;
            size_t grow = (size_t)tile * 128 + r;
            uint4* dst = (uint4*)(g_cst2h + grow * 64);
            const __nv_bfloat16* src = sA + r * LDB;
#pragma unroll
            for (int j = 0; j < 4; j++)
                dst[j0 + j] = *(const uint4*)(src + (j0 + j) * 8);
        }
    }
}

// ---------- K3: triplet kernel, 2/warp, batched loads, early sg loads ----------
__global__ void __launch_bounds__(256) k_tri(const float* __restrict__ rb,
                                             const float* __restrict__ shb,
                                             const int*   __restrict__ tri_k,
                                             const int*   __restrict__ eks,
                                             const int*   __restrict__ est) {
    int w = (blockIdx.x * blockDim.x + threadIdx.x) >> 5;
    int lane = threadIdx.x & 31;
    int t0 = 2 * w, t1 = 2 * w + 1;
    if (t0 >= N_TRI) return;

    int e0 = eks[t0], k0 = tri_k[t0], o0 = est[t0];
    int e1 = eks[t1], k1 = tri_k[t1], o1 = est[t1];

    float cl0 = (lane < NORB) ? rb[(size_t)e0 * NORB + lane] * shb[(size_t)t0 * NORB + lane] : 0.f;
    float cl1 = (lane < NORB) ? rb[(size_t)e1 * NORB + lane] * shb[(size_t)t1 * NORB + lane] : 0.f;

    float2 sg0 = *(const float2*)(g_xksig + (size_t)k0 * CONV + 2 * lane);
    float2 sg1 = *(const float2*)(g_xksig + (size_t)k1 * CONV + 2 * lane);

    const uint32_t* C0 = (const uint32_t*)(g_cst2h + (size_t)e0 * (NORB * CONV));
    const uint32_t* C1 = (const uint32_t*)(g_cst2h + (size_t)e1 * (NORB * CONV));
    uint32_t r0[NORB], r1[NORB];
#pragma unroll
    for (int d = 0; d < NORB; d++) r0[d] = C0[d * 32 + lane];
#pragma unroll
    for (int d = 0; d < NORB; d++) r1[d] = C1[d * 32 + lane];

    float a0 = 0.f, a1 = 0.f, b0 = 0.f, b1 = 0.f;
#pragma unroll
    for (int d = 0; d < NORB; d++) {
        float c0 = __shfl_sync(0xffffffffu, cl0, d);
        float c1 = __shfl_sync(0xffffffffu, cl1, d);
        float2 v0 = __bfloat1622float2(*(const __nv_bfloat162*)&r0[d]);
        float2 v1 = __bfloat1622float2(*(const __nv_bfloat162*)&r1[d]);
        a0 = fmaf(c0, v0.x, a0);
        a1 = fmaf(c0, v0.y, a1);
        b0 = fmaf(c1, v1.x, b0);
        b1 = fmaf(c1, v1.y, b1);
    }
    float sa = a0 * a0 + a1 * a1;
    float sbb = b0 * b0 + b1 * b1;
#pragma unroll
    for (int o = 16; o; o >>= 1) {
        sa  += __shfl_xor_sync(0xffffffffu, sa, o);
        sbb += __shfl_xor_sync(0xffffffffu, sbb, o);
    }
    float ia = 1.f / fmaxf(sqrtf(sa), 1e-12f);
    float ib = 1.f / fmaxf(sqrtf(sbb), 1e-12f);

    red2(&g_tbw[(size_t)o0 * CONV + 2 * lane], a0 * ia * sg0.x, a1 * ia * sg0.y);
    red2(&g_tbw[(size_t)o1 * CONV + 2 * lane], b0 * ib * sg1.x, b1 * ib * sg1.y);
}

// ---------- K4: persistent bf16 mma edge kernel (R13 form) ----------
#define E_W3   0
#define E_WB   4608
#define E_WN2  9216
#define E_WN1  13824
#define E_TW   22528
#define E_CAT  31744
#define E_END  49152
#define LDC    136
#define EDGE_SMEM_BYTES (E_END * 2 + 512 + 1024)
__global__ void __launch_bounds__(256, 2) k_edge(const int* __restrict__ idx_s,
                                                 const int* __restrict__ idx_t,
                                                 const float* __restrict__ W3g,
                                                 const float* __restrict__ Wbg,
                                                 const float* __restrict__ Wn1g,
                                                 const float* __restrict__ bn1g,
                                                 const float* __restrict__ Wn2g,
                                                 const float* __restrict__ bn2g) {
    extern __shared__ __align__(16) __nv_bfloat16 sb[];
    __nv_bfloat16* sW3  = sb + E_W3;
    __nv_bfloat16* sWB  = sb + E_WB;
    __nv_bfloat16* sWN2 = sb + E_WN2;
    __nv_bfloat16* sWN1 = sb + E_WN1;
    __nv_bfloat16* sTW  = sb + E_TW;
    __nv_bfloat16* sCAT = sb + E_CAT;
    float* b1s = (float*)(sb + E_END);
    float* b2s = b1s + 64;
    int*   es  = (int*)(b2s + 64);
    int*   et  = es + 128;
    const uint32_t sW3u  = smem_u32(sW3);
    const uint32_t sWBu  = smem_u32(sWB);
    const uint32_t sWN2u = smem_u32(sWN2);
    const uint32_t sWN1u = smem_u32(sWN1);
    const uint32_t sTWu  = smem_u32(sTW);
    const uint32_t sCATu = smem_u32(sCAT);

    const int tid = threadIdx.x, wid = tid >> 5, lane = tid & 31;
    const int g = lane >> 2, tg = lane & 3;
    const int wr0 = wid * 16;

    for (int i = tid; i < 4096; i += 256) {
        int k = i >> 6, n = i & 63;
        sW3 [n * LDB + k] = __float2bfloat16(W3g[i]);
        sWB [n * LDB + k] = __float2bfloat16(Wbg[i]);
        sWN2[n * LDB + k] = __float2bfloat16(Wn2g[i]);
    }
    for (int i = tid; i < 8192; i += 256) {
        int k = i >> 6, n = i & 63;
        sWN1[n * LDC + k] = __float2bfloat16(Wn1g[i]);
    }
    if (tid < 64) { b1s[tid] = bn1g[tid]; b2s[tid] = bn2g[tid]; }

    const uint32_t a_offB = A_OFF(lane, LDB);
    const uint32_t b_offB = B_OFF(lane, LDB);
    const uint32_t a_offC = A_OFF(lane, LDC);
    const uint32_t b_offC = B_OFF(lane, LDC);

    for (int tile = blockIdx.x; tile < N_ETILES; tile += PGRID_E) {
        const int e0 = tile * 128;
        __syncthreads();

        if (tid < 128) {
            int e = e0 + tid;
            es[tid] = (e < N_EDGES) ? idx_s[e] : 0;
            et[tid] = (e < N_EDGES) ? idx_t[e] : 0;
        }
        for (int i = tid; i < 2048; i += 256) {
            int r = i >> 4, c4 = i & 15;
            float4 v = (e0 + r < N_EDGES) ? ((const float4*)g_tbw)[(size_t)(e0 + r) * 16 + c4]
                                          : make_float4(0.f, 0.f, 0.f, 0.f);
            *(uint2*)(sTW + r * LDB + c4 * 4) = make_uint2(bf2x(v.x, v.y), bf2x(v.z, v.w));
        }
        __syncthreads();

        for (int i = tid; i < 4096; i += 256) {
            int r = i >> 5, c4 = i & 31;
            int node = (c4 < 16) ? es[r] : et[r];
            float4 v = (e0 + r < N_EDGES) ? ((const float4*)g_x1)[(size_t)node * 16 + (c4 & 15)]
                                          : make_float4(0.f, 0.f, 0.f, 0.f);
            *(uint2*)(sCAT + r * LDC + c4 * 4) = make_uint2(bf2x(v.x, v.y), bf2x(v.z, v.w));
        }

        float acc[8][4];
        uint32_t a[4];
        uint32_t la[4][4];
        uint32_t na[4][4];

        // ---- GEMM1: proj = tw @ W3 -> lc (overlaps cat gather) ----
#pragma unroll
        for (int at = 0; at < 8; at++)
#pragma unroll
            for (int q = 0; q < 4; q++) acc[at][q] = 0.f;
#pragma unroll
        for (int ks = 0; ks < 4; ks++) {
            const int k0 = ks * 16;
            ldmx4(a[0], a[1], a[2], a[3], sTWu + a_offB + (uint32_t)(wr0 * LDB + k0) * 2);
#pragma unroll
            for (int np = 0; np < 4; np++) {
                uint32_t b0, b1, b2, b3;
                ldmx4(b0, b1, b2, b3, sW3u + b_offB + (uint32_t)(np * 16 * LDB + k0) * 2);
                mma_bf16(acc[2 * np],     a, b0, b1);
                mma_bf16(acc[2 * np + 1], a, b2, b3);
            }
        }
        {
            size_t eg  = (size_t)(e0 + wr0 + g);
            size_t eg8 = eg + 8;
            bool ok0 = eg  < N_EDGES;
            bool ok8 = eg8 < N_EDGES;
            float s0 = 0.f, s8 = 0.f;
#pragma unroll
            for (int at = 0; at < 8; at++) {
                int c = at * 8 + 2 * tg;
                float2 l0 = ok0 ? *(const float2*)&g_lraw[eg * CONV + c]  : make_float2(0.f, 0.f);
                float2 l8 = ok8 ? *(const float2*)&g_lraw[eg8 * CONV + c] : make_float2(0.f, 0.f);
                acc[at][0] = l0.x * (1.f + acc[at][0]);
                acc[at][1] = l0.y * (1.f + acc[at][1]);
                acc[at][2] = l8.x * (1.f + acc[at][2]);
                acc[at][3] = l8.y * (1.f + acc[at][3]);
                s0 += acc[at][0] * acc[at][0] + acc[at][1] * acc[at][1];
                s8 += acc[at][2] * acc[at][2] + acc[at][3] * acc[at][3];
            }
#pragma unroll
            for (int o = 1; o < 4; o <<= 1) {
                s0 += __shfl_xor_sync(0xffffffffu, s0, o);
                s8 += __shfl_xor_sync(0xffffffffu, s8, o);
            }
            float i0 = 1.f / fmaxf(sqrtf(s0), 1e-12f);
            float i8 = 1.f / fmaxf(sqrtf(s8), 1e-12f);
#pragma unroll
            for (int at = 0; at < 8; at++) {
                acc[at][0] *= i0; acc[at][1] *= i0;
                acc[at][2] *= i8; acc[at][3] *= i8;
            }
#pragma unroll
            for (int ks = 0; ks < 4; ks++) PACK_A(la[ks], acc, ks);
        }
        __syncthreads();

        // ---- GEMM2: n1 = silu(cat @ Wn1 + b1) ----
#pragma unroll
        for (int at = 0; at < 8; at++) {
            int c = at * 8 + 2 * tg;
            acc[at][0] = b1s[c]; acc[at][1] = b1s[c + 1];
            acc[at][2] = acc[at][0]; acc[at][3] = acc[at][1];
        }
#pragma unroll
        for (int ks = 0; ks < 8; ks++) {
            const int k0 = ks * 16;
            ldmx4(a[0], a[1], a[2], a[3], sCATu + a_offC + (uint32_t)(wr0 * LDC + k0) * 2);
#pragma unroll
            for (int np = 0; np < 4; np++) {
                uint32_t b0, b1, b2, b3;
                ldmx4(b0, b1, b2, b3, sWN1u + b_offC + (uint32_t)(np * 16 * LDC + k0) * 2);
                mma_bf16(acc[2 * np],     a, b0, b1);
                mma_bf16(acc[2 * np + 1], a, b2, b3);
            }
        }
#pragma unroll
        for (int at = 0; at < 8; at++)
#pragma unroll
            for (int q = 0; q < 4; q++) acc[at][q] = silu_f(acc[at][q]);
#pragma unroll
        for (int ks = 0; ks < 4; ks++) PACK_A(na[ks], acc, ks);

        // ---- GEMM3: nf = silu(n1 @ Wn2 + b2) ----
        float nf[8][4];
#pragma unroll
        for (int at = 0; at < 8; at++) {
            int c = at * 8 + 2 * tg;
            nf[at][0] = b2s[c]; nf[at][1] = b2s[c + 1];
            nf[at][2] = nf[at][0]; nf[at][3] = nf[at][1];
        }
#pragma unroll
        for (int ks = 0; ks < 4; ks++) {
            const int k0 = ks * 16;
#pragma unroll
            for (int np = 0; np < 4; np++) {
                uint32_t b0, b1, b2, b3;
                ldmx4(b0, b1, b2, b3, sWN2u + b_offB + (uint32_t)(np * 16 * LDB + k0) * 2);
                mma_bf16(nf[2 * np],     na[ks], b0, b1);
                mma_bf16(nf[2 * np + 1], na[ks], b2, b3);
            }
        }
#pragma unroll
        for (int at = 0; at < 8; at++)
#pragma unroll
            for (int q = 0; q < 4; q++) nf[at][q] = silu_f(nf[at][q]);

        // ---- GEMM4: m = lc @ Wb ----
#pragma unroll
        for (int at = 0; at < 8; at++)
#pragma unroll
            for (int q = 0; q < 4; q++) acc[at][q] = 0.f;
#pragma unroll
        for (int ks = 0; ks < 4; ks++) {
            const int k0 = ks * 16;
#pragma unroll
            for (int np = 0; np < 4; np++) {
                uint32_t b0, b1, b2, b3;
                ldmx4(b0, b1, b2, b3, sWBu + b_offB + (uint32_t)(np * 16 * LDB + k0) * 2);
                mma_bf16(acc[2 * np],     la[ks], b0, b1);
                mma_bf16(acc[2 * np + 1], la[ks], b2, b3);
            }
        }

        // ---- scatter msg = m * nf by idx_s ----
        {
            int rg = wr0 + g;
            int ns0 = es[rg], ns8 = es[rg + 8];
            bool ok0 = (e0 + rg) < N_EDGES;
            bool ok8 = (e0 + rg + 8) < N_EDGES;
#pragma unroll
            for (int at = 0; at < 8; at++) {
                int c = at * 8 + 2 * tg;
                if (ok0) red2(&g_agg[(size_t)ns0 * CONV + c],
                              acc[at][0] * nf[at][0], acc[at][1] * nf[at][1]);
                if (ok8) red2(&g_agg[(size_t)ns8 * CONV + c],
                              acc[at][2] * nf[at][2], acc[at][3] * nf[at][3]);
            }
        }
    }
}

// ---------- K5: out = x + agg @ W_out, 16 nodes/block (R13 form) ----------
#define NPB 16
__global__ void __launch_bounds__(128) k_out(const float* __restrict__ x,
                                             const float* __restrict__ Wout,
                                             float* __restrict__ out) {
    __shared__ float ags[NPB][CONV];
    const int n0 = blockIdx.x * NPB, j = threadIdx.x;
    ((float4*)ags)[j]       = ((const float4*)g_agg)[(size_t)blockIdx.x * 256 + j];
    ((float4*)ags)[j + 128] = ((const float4*)g_agg)[(size_t)blockIdx.x * 256 + j + 128];
    __syncthreads();
    float acc[NPB];
#pragma unroll
    for (int v = 0; v < NPB; v++) acc[v] = 0.f;
#pragma unroll 4
    for (int k = 0; k < CONV; k++) {
        float w = Wout[k * EMB + j];
#pragma unroll
        for (int v = 0; v < NPB; v++) acc[v] = fmaf(ags[v][k], w, acc[v]);
    }
#pragma unroll
    for (int v = 0; v < NPB; v++)
        out[(size_t)(n0 + v) * EMB + j] = x[(size_t)(n0 + v) * EMB + j] + acc[v];
}

extern "C" void kernel_launch(void* const* d_in, const int* in_sizes, int n_in,
                              void* d_out, int out_size) {
    const float* x      = (const float*)d_in[0];
    const float* cst    = (const float*)d_in[1];
    const float* rb     = (const float*)d_in[2];
    const float* shb    = (const float*)d_in[3];
    const int*   idx_s  = (const int*)  d_in[4];
    const int*   idx_t  = (const int*)  d_in[5];
    const int*   tri_k  = (const int*)  d_in[6];
    const int*   eks    = (const int*)  d_in[7];
    const int*   est    = (const int*)  d_in[8];
    const float* W_node = (const float*)d_in[9];
    const float* b_node = (const float*)d_in[10];
    const float* W_c1   = (const float*)d_in[11];
    const float* W_c2   = (const float*)d_in[12];
    const float* W_three= (const float*)d_in[13];
    const float* W_basis= (const float*)d_in[14];
    const float* W_n1   = (const float*)d_in[15];
    const float* b_n1   = (const float*)d_in[16];
    const float* W_n2   = (const float*)d_in[17];
    const float* b_n2   = (const float*)d_in[18];
    const float* W_out  = (const float*)d_in[19];
    float* out = (float*)d_out;

    cudaFuncSetAttribute(k_edge,    cudaFuncAttributeMaxDynamicSharedMemorySize, EDGE_SMEM_BYTES);
    cudaFuncSetAttribute(k_cst_mma, cudaFuncAttributeMaxDynamicSharedMemorySize, CST_SMEM_BYTES);

    k_cst_mma<<<PGRID, 256, CST_SMEM_BYTES>>>(cst, rb, x, W_node, b_node, W_c1, W_c2);
    k_tri <<<N_TRI / 16, 256>>>(rb, shb, tri_k, eks, est);
    k_edge<<<PGRID_E, 256, EDGE_SMEM_BYTES>>>(idx_s, idx_t, W_three, W_basis,
                                              W_n1, b_n1, W_n2, b_n2);
    k_out <<<N_NODES / NPB, 128>>>(x, W_out, out);
}